// round 4
// baseline (speedup 1.0000x reference)
#include <cuda_runtime.h>
#include <math.h>

#define N_CLUS 64
#define C_DIM 768
#define B_DIM 8
#define H_IN 32
#define HW 1024                          // 32*32
#define OUT_HW 512
#define PLANE (OUT_HW * OUT_HW)          // 262144
#define NPIX (B_DIM * HW)                // 8192
#define RES_ELEMS ((size_t)B_DIM * N_CLUS * PLANE)   // 134217728
#define CODE_ELEMS ((size_t)B_DIM * C_DIM * HW)      // 6291456
#define KC 32

#define SIM_BLOCKS 128
#define ZERO_BLOCKS 1792
#define COPY_BLOCKS 128
#define A_BLOCKS (SIM_BLOCKS + ZERO_BLOCKS + COPY_BLOCKS)
// zero region = floats [1, 1+RES_ELEMS) of out. Head scalars 1,2,3; aligned
// float4 span floats [4, 134217728) = 33554431 float4s; tail scalar 134217728.
#define NQ4 33554431LL

__device__ int   g_assign[NPIX];
__device__ float g_maxcos[NPIX];

// ---------------------------------------------------------------------------
// Kernel A (block-specialized fusion):
//   blocks [0,128):        sims + argmax + feature norm (64 px x 64 clusters)
//   blocks [128,1920):     float4 zero-fill of resized region (aligned STG.128)
//   blocks [1920,2048):    code passthrough copy
// Compute-bound sim blocks hide under the DRAM-bound streaming blocks.
// ---------------------------------------------------------------------------
__global__ __launch_bounds__(256) void fusedA(const float* __restrict__ code,
                                              const float* __restrict__ clusters,
                                              float* __restrict__ out) {
    const int tid = threadIdx.x;
    const int blk = blockIdx.x;

    if (blk >= SIM_BLOCKS) {
        if (blk < SIM_BLOCKS + ZERO_BLOCKS) {
            // ---- dense zero-fill, 16B-aligned vector stores ----
            const int id = blk - SIM_BLOCKS;
            float4* o4 = (float4*)out;          // out assumed 16B aligned
            const float4 z = make_float4(0.f, 0.f, 0.f, 0.f);
            for (long long q = (long long)id * 256 + tid; q < NQ4;
                 q += (long long)ZERO_BLOCKS * 256)
                o4[1 + q] = z;                  // floats [4, 134217728)
            if (id == 0 && tid < 4) {           // edge scalars
                out[(tid == 3) ? 134217728u : (1u + tid)] = 0.f;
            }
        } else {
            // ---- code passthrough ----
            const int id = blk - SIM_BLOCKS - ZERO_BLOCKS;
            float* dst = out + 1 + RES_ELEMS;
            for (long long i = (long long)id * 256 + tid; i < (long long)CODE_ELEMS;
                 i += (long long)COPY_BLOCKS * 256)
                dst[i] = __ldg(code + i);
        }
        return;
    }

    // ---- sim branch: block = 64 pixels x all 64 clusters ----
    __shared__ __align__(16) float codeS[KC][64];
    __shared__ float clusS[N_CLUS][KC + 1];     // +1 pad: kill 4-row bank alias
    __shared__ float sinv[N_CLUS];
    __shared__ float smv[16][64];
    __shared__ int   smn[16][64];
    __shared__ float ssqS[64];

    // cluster inverse norms (4 threads per cluster, shfl reduce)
    {
        const int n = tid >> 2, q = tid & 3;
        const float* cr = clusters + n * C_DIM + q * 192;
        float s = 0.f;
#pragma unroll 8
        for (int i = 0; i < 192; ++i) s = fmaf(cr[i], cr[i], s);
        s += __shfl_xor_sync(0xffffffffu, s, 1);
        s += __shfl_xor_sync(0xffffffffu, s, 2);
        if (q == 0) sinv[n] = 1.f / fmaxf(sqrtf(s), 1e-12f);
    }
    __syncthreads();

    const int b = blk >> 4;                  // 16 blocks per image
    const int hwbase = (blk & 15) * 64;
    const int pid = tid & 15;                // 4 pixels: 4*pid .. 4*pid+3
    const int ng = tid >> 4;                 // 4 clusters: ng*4 .. ng*4+3
    const float* codeb = code + (size_t)b * C_DIM * HW + hwbase;

    float acc[4][4];
#pragma unroll
    for (int j = 0; j < 4; ++j)
#pragma unroll
        for (int p = 0; p < 4; ++p) acc[j][p] = 0.f;
    float ssq[4] = {0.f, 0.f, 0.f, 0.f};

    for (int c0 = 0; c0 < C_DIM; c0 += KC) {
#pragma unroll
        for (int k = 0; k < 8; ++k) {        // stage code [KC][64], coalesced
            int idx = tid + k * 256;
            int c = idx >> 6, px = idx & 63;
            codeS[c][px] = codeb[(size_t)(c0 + c) * HW + px];
        }
#pragma unroll
        for (int k = 0; k < 8; ++k) {        // stage normalized clusters [64][KC]
            int idx = tid + k * 256;
            int n = idx >> 5, c = idx & 31;
            clusS[n][c] = clusters[n * C_DIM + c0 + c] * sinv[n];
        }
        __syncthreads();

#pragma unroll 4
        for (int c = 0; c < KC; ++c) {
            float4 a = *(const float4*)&codeS[c][4 * pid];
            if (ng == 0) {                   // fold feature sumsq into pass
                ssq[0] = fmaf(a.x, a.x, ssq[0]);
                ssq[1] = fmaf(a.y, a.y, ssq[1]);
                ssq[2] = fmaf(a.z, a.z, ssq[2]);
                ssq[3] = fmaf(a.w, a.w, ssq[3]);
            }
#pragma unroll
            for (int j = 0; j < 4; ++j) {
                float bv = clusS[ng * 4 + j][c];
                acc[j][0] = fmaf(a.x, bv, acc[j][0]);
                acc[j][1] = fmaf(a.y, bv, acc[j][1]);
                acc[j][2] = fmaf(a.z, bv, acc[j][2]);
                acc[j][3] = fmaf(a.w, bv, acc[j][3]);
            }
        }
        __syncthreads();
    }

    // thread-local argmax over 4 clusters per pixel (ascending => first-max)
#pragma unroll
    for (int p = 0; p < 4; ++p) {
        float mv = acc[0][p];
        int mn = ng * 4;
#pragma unroll
        for (int j = 1; j < 4; ++j)
            if (acc[j][p] > mv) { mv = acc[j][p]; mn = ng * 4 + j; }
        smv[ng][4 * pid + p] = mv;
        smn[ng][4 * pid + p] = mn;
        if (ng == 0) ssqS[4 * pid + p] = ssq[p];
    }
    __syncthreads();

    if (tid < 64) {
        float best = smv[0][tid];
        int bn = smn[0][tid];
#pragma unroll
        for (int g = 1; g < 16; ++g)         // ascending groups => first-max
            if (smv[g][tid] > best) { best = smv[g][tid]; bn = smn[g][tid]; }
        const int gp = blk * 64 + tid;       // = b*1024 + (blk&15)*64 + tid
        g_assign[gp] = bn;
        g_maxcos[gp] = best / fmaxf(sqrtf(ssqS[tid]), 1e-12f);
    }
}

// ---------------------------------------------------------------------------
// Kernel B: sparse bilinear scatter (<=4 nonzeros per output (y,x)) + loss.
// Grid: 4096 blocks = (b=8, y=512), 128 threads, thread handles 4 x's.
// Block 4096 = deterministic loss reduction.
// ---------------------------------------------------------------------------
__global__ __launch_bounds__(128) void scatterB(float* __restrict__ out) {
    const int blk = blockIdx.x;
    if (blk == B_DIM * OUT_HW) {             // loss block
        __shared__ float red[128];
        float s = 0.f;
        for (int i = threadIdx.x; i < NPIX; i += 128) s += g_maxcos[i];
        red[threadIdx.x] = s;
        __syncthreads();
        for (int o = 64; o > 0; o >>= 1) {
            if (threadIdx.x < o) red[threadIdx.x] += red[threadIdx.x + o];
            __syncthreads();
        }
        if (threadIdx.x == 0) out[0] = -red[0] / (float)NPIX;
        return;
    }

    const int b = blk >> 9;
    const int y = blk & 511;
    const float fy = (y + 0.5f) * 0.0625f - 0.5f;
    const float y0f = floorf(fy);
    const float wy1 = fy - y0f;
    const float wy0 = 1.f - wy1;
    const int y0 = (int)y0f;
    const int ylo = max(y0, 0), yhi = min(y0 + 1, H_IN - 1);
    const int* arow0 = g_assign + b * HW + ylo * H_IN;
    const int* arow1 = g_assign + b * HW + yhi * H_IN;
    float* ob = out + 1 + (size_t)b * N_CLUS * PLANE + (size_t)y * OUT_HW;

#pragma unroll
    for (int xi = 0; xi < 4; ++xi) {
        const int x = threadIdx.x + xi * 128;   // warp => consecutive x, coalesced
        const float fx = (x + 0.5f) * 0.0625f - 0.5f;
        const float x0f = floorf(fx);
        const float wx1 = fx - x0f;
        const float wx0 = 1.f - wx1;
        const int x0 = (int)x0f;
        const int xlo = max(x0, 0), xhi = min(x0 + 1, H_IN - 1);

        int n[4];
        float w[4];
        n[0] = arow0[xlo]; w[0] = wy0 * wx0;
        n[1] = arow0[xhi]; w[1] = wy0 * wx1;
        n[2] = arow1[xlo]; w[2] = wy1 * wx0;
        n[3] = arow1[xhi]; w[3] = wy1 * wx1;

        // merge duplicate cluster ids (each (b,n,y,x) written by one thread)
        bool v[4] = {true, true, true, true};
#pragma unroll
        for (int i = 1; i < 4; ++i)
#pragma unroll
            for (int j = 0; j < i; ++j)
                if (v[i] && v[j] && n[i] == n[j]) { w[j] += w[i]; v[i] = false; }

#pragma unroll
        for (int i = 0; i < 4; ++i)
            if (v[i]) ob[(size_t)n[i] * PLANE + x] = w[i];
    }
}

// ---------------------------------------------------------------------------
// out layout = [loss(1)] [resized(134217728)] [code(6291456)]
// ---------------------------------------------------------------------------
extern "C" void kernel_launch(void* const* d_in, const int* in_sizes, int n_in,
                              void* d_out, int out_size) {
    const float* code = (const float*)d_in[0];
    const float* clusters = (const float*)d_in[1];
    float* out = (float*)d_out;

    fusedA<<<A_BLOCKS, 256>>>(code, clusters, out);
    scatterB<<<B_DIM * OUT_HW + 1, 128>>>(out);
}